// round 1
// baseline (speedup 1.0000x reference)
#include <cuda_runtime.h>
#include <math.h>

#define NN 100000
#define NE 1600000
#define NG 200
#define HID 64

// ---------------- scratch (static device globals; no allocation) ----------------
__device__ int   g_deg[NN];
__device__ int   g_incl[NN];
__device__ int   g_rowptr[NN + 1];
__device__ int   g_cur[NN];
__device__ int   g_bsums[256];
__device__ int   g_csr[NE];
__device__ float g_hA[NN * HID];
__device__ float g_hB[NN * HID];
__device__ float g_agg[NN * 128];
__device__ float g_obuf[NG * 196];

__device__ __forceinline__ float silu_f(float z) { return z / (1.f + __expf(-z)); }

// ---------------- CSR build ----------------
__global__ void zero_deg_kernel(int* deg) {
    int i = blockIdx.x * blockDim.x + threadIdx.x;
    if (i < NN) deg[i] = 0;
}

__global__ void hist_kernel(const int* __restrict__ ei, int* __restrict__ deg) {
    int e = blockIdx.x * blockDim.x + threadIdx.x;
    if (e < NE) atomicAdd(&deg[ei[NE + e]], 1);
}

__global__ void scan1_kernel(const int* __restrict__ deg, int* __restrict__ incl,
                             int* __restrict__ bsums) {
    __shared__ int s[1024];
    int tid = threadIdx.x;
    int i = blockIdx.x * 1024 + tid;
    s[tid] = (i < NN) ? deg[i] : 0;
    __syncthreads();
    for (int off = 1; off < 1024; off <<= 1) {
        int v = (tid >= off) ? s[tid - off] : 0;
        __syncthreads();
        s[tid] += v;
        __syncthreads();
    }
    if (i < NN) incl[i] = s[tid];
    if (tid == 1023) bsums[blockIdx.x] = s[1023];
}

__global__ void scan2_kernel(int* bsums, int nb) {
    if (threadIdx.x == 0 && blockIdx.x == 0) {
        int run = 0;
        for (int b = 0; b < nb; b++) { int t = bsums[b]; bsums[b] = run; run += t; }
    }
}

__global__ void scan3_kernel(const int* __restrict__ incl, const int* __restrict__ deg,
                             const int* __restrict__ bsums, int* __restrict__ rowptr,
                             int* __restrict__ cur) {
    int i = blockIdx.x * blockDim.x + threadIdx.x;
    if (i < NN) {
        int val = incl[i] + bsums[i >> 10];
        rowptr[i + 1] = val;
        cur[i] = val - deg[i];
    }
    if (i == 0) rowptr[0] = 0;
}

__global__ void scatter_kernel(const int* __restrict__ ei, int* __restrict__ cur,
                               int* __restrict__ csr) {
    int e = blockIdx.x * blockDim.x + threadIdx.x;
    if (e < NE) {
        int d = ei[NE + e];
        int p = atomicAdd(&cur[d], 1);
        csr[p] = ei[e];
    }
}

// ---------------- layer 0 (IN=4): fully fused sage + LN + x_res + silu ----------------
__global__ __launch_bounds__(256) void layer0_kernel(
    const float* __restrict__ x, const int* __restrict__ rowptr, const int* __restrict__ csr,
    const float* __restrict__ Wl0, const float* __restrict__ bl0, const float* __restrict__ Wr0,
    const float* __restrict__ Wres, const float* __restrict__ bres,
    const float* __restrict__ lng, const float* __restrict__ lnb, float* __restrict__ hout) {
    int tid = threadIdx.x;
    int grp = tid >> 6;
    int l = tid & 63;
    int v = blockIdx.x * 4 + grp;
    bool valid = (v < NN);
    __shared__ float sMx[4][64], sSm[4][64], sAgg[4][8], sX[4][4], sP[4][2][2];
    int start = 0, end = 0;
    if (valid) { start = rowptr[v]; end = rowptr[v + 1]; }
    if (valid && l < 4) sX[grp][l] = x[v * 4 + l];
    int es = l >> 2, dim = l & 3;
    float mx = -INFINITY, sm = 0.f;
    for (int e = start + es; e < end; e += 16) {
        int s = csr[e];
        float val = x[s * 4 + dim];
        mx = fmaxf(mx, val);
        sm += val;
    }
    sMx[grp][l] = mx; sSm[grp][l] = sm;
    __syncthreads();
    if (l < 8) {
        int dd = l & 3;
        int deg = end - start;
        if (l < 4) {
            float m = -INFINITY;
            #pragma unroll
            for (int j = 0; j < 16; j++) m = fmaxf(m, sMx[grp][j * 4 + dd]);
            sAgg[grp][dd] = (deg > 0) ? m : 0.f;
        } else {
            float s2 = 0.f;
            #pragma unroll
            for (int j = 0; j < 16; j++) s2 += sSm[grp][j * 4 + dd];
            sAgg[grp][4 + dd] = s2 / (float)(deg > 0 ? deg : 1);
        }
    }
    __syncthreads();
    float acc = __ldg(bl0 + l);
    #pragma unroll
    for (int k = 0; k < 8; k++) acc += sAgg[grp][k] * __ldg(Wl0 + k * 64 + l);
    float xres = __ldg(bres + l);
    #pragma unroll
    for (int k = 0; k < 4; k++) {
        float xv = sX[grp][k];
        acc += xv * __ldg(Wr0 + k * 64 + l);
        xres += xv * __ldg(Wres + k * 64 + l);
    }
    float s1 = acc, q1 = acc * acc;
    #pragma unroll
    for (int m2 = 1; m2 < 32; m2 <<= 1) {
        s1 += __shfl_xor_sync(0xffffffffu, s1, m2);
        q1 += __shfl_xor_sync(0xffffffffu, q1, m2);
    }
    int w = (tid >> 5) & 1;
    if ((tid & 31) == 0) { sP[grp][w][0] = s1; sP[grp][w][1] = q1; }
    __syncthreads();
    float S = sP[grp][0][0] + sP[grp][1][0];
    float Q = sP[grp][0][1] + sP[grp][1][1];
    float mean = S * (1.f / 64.f);
    float var = Q * (1.f / 64.f) - mean * mean;
    float rstd = rsqrtf(var + 1e-5f);
    float z = (acc - mean) * rstd * __ldg(lng + l) + __ldg(lnb + l) + xres;
    if (valid) hout[v * 64 + l] = silu_f(z);
}

// ---------------- aggregation (hidden layers): writes [mx|mean] (128) per node ----------------
__global__ __launch_bounds__(256) void agg_kernel(const float* __restrict__ hin,
                                                  const int* __restrict__ rowptr,
                                                  const int* __restrict__ csr,
                                                  float* __restrict__ aggout) {
    int tid = threadIdx.x;
    int grp = tid >> 6;
    int l = tid & 63;
    int v = blockIdx.x * 4 + grp;
    if (v >= NN) return;
    int start = rowptr[v], end = rowptr[v + 1];
    float mx = -INFINITY, sm = 0.f;
    int e = start;
    for (; e + 4 <= end; e += 4) {
        int s0 = csr[e], s1 = csr[e + 1], s2 = csr[e + 2], s3 = csr[e + 3];
        float v0 = hin[s0 * 64 + l], v1 = hin[s1 * 64 + l];
        float v2 = hin[s2 * 64 + l], v3 = hin[s3 * 64 + l];
        mx = fmaxf(fmaxf(fmaxf(fmaxf(mx, v0), v1), v2), v3);
        sm += (v0 + v1) + (v2 + v3);
    }
    for (; e < end; e++) {
        float vv = hin[csr[e] * 64 + l];
        mx = fmaxf(mx, vv);
        sm += vv;
    }
    int deg = end - start;
    aggout[v * 128 + l] = (deg > 0) ? mx : 0.f;
    aggout[v * 128 + 64 + l] = sm / (float)(deg > 0 ? deg : 1);
}

// ---------------- sage GEMM + LN + residual + silu (hidden layers) ----------------
// M=NN, A=[agg(128)|hin(64)], W=[Wl;Wr] (192x64), fused epilogue. Tile BM=64, N=64.
#define GEMM_SMEM ((128 * 64 + 64 * 64 + 64 * 132 + 64 * 68) * 4)
__global__ __launch_bounds__(256) void sage_gemm_kernel(
    const float* __restrict__ agg, const float* __restrict__ hin,
    const float* __restrict__ Wl, const float* __restrict__ bl, const float* __restrict__ Wr,
    const float* __restrict__ lng, const float* __restrict__ lnb, float* __restrict__ hout) {
    extern __shared__ float smem[];
    float* sWl = smem;                 // 128*64
    float* sWr = sWl + 128 * 64;       // 64*64
    float* sA = sWr + 64 * 64;         // 64 x 132
    float* sH = sA + 64 * 132;         // 64 x 68
    int tid = threadIdx.x;
    for (int i = tid; i < 128 * 64 / 4; i += 256) ((float4*)sWl)[i] = ((const float4*)Wl)[i];
    for (int i = tid; i < 64 * 64 / 4; i += 256) ((float4*)sWr)[i] = ((const float4*)Wr)[i];
    int ty = tid >> 4, tx = tid & 15;
    float4 bv = *(const float4*)(bl + tx * 4);
    float4 gv = *(const float4*)(lng + tx * 4);
    float4 lbv = *(const float4*)(lnb + tx * 4);
    const int NT = (NN + 63) >> 6;
    for (int t = blockIdx.x; t < NT; t += gridDim.x) {
        __syncthreads();
        int base = t * 64;
        for (int i = tid; i < 2048; i += 256) {
            int r = i >> 5, c = i & 31;
            float4 vv = make_float4(0.f, 0.f, 0.f, 0.f);
            int row = base + r;
            if (row < NN) vv = ((const float4*)(agg + (long)row * 128))[c];
            ((float4*)(sA + r * 132))[c] = vv;
        }
        for (int i = tid; i < 1024; i += 256) {
            int r = i >> 4, c = i & 15;
            float4 vv = make_float4(0.f, 0.f, 0.f, 0.f);
            int row = base + r;
            if (row < NN) vv = ((const float4*)(hin + (long)row * 64))[c];
            ((float4*)(sH + r * 68))[c] = vv;
        }
        __syncthreads();
        float acc[4][4];
        #pragma unroll
        for (int i = 0; i < 4; i++)
            #pragma unroll
            for (int j = 0; j < 4; j++) acc[i][j] = 0.f;
        #pragma unroll 8
        for (int k = 0; k < 128; k++) {
            float4 wv = *(float4*)(sWl + k * 64 + tx * 4);
            #pragma unroll
            for (int i = 0; i < 4; i++) {
                float a = sA[(ty * 4 + i) * 132 + k];
                acc[i][0] += a * wv.x; acc[i][1] += a * wv.y;
                acc[i][2] += a * wv.z; acc[i][3] += a * wv.w;
            }
        }
        #pragma unroll 8
        for (int k = 0; k < 64; k++) {
            float4 wv = *(float4*)(sWr + k * 64 + tx * 4);
            #pragma unroll
            for (int i = 0; i < 4; i++) {
                float a = sH[(ty * 4 + i) * 68 + k];
                acc[i][0] += a * wv.x; acc[i][1] += a * wv.y;
                acc[i][2] += a * wv.z; acc[i][3] += a * wv.w;
            }
        }
        #pragma unroll
        for (int i = 0; i < 4; i++) {
            float v0 = acc[i][0] + bv.x;
            float v1 = acc[i][1] + bv.y;
            float v2 = acc[i][2] + bv.z;
            float v3 = acc[i][3] + bv.w;
            float s = (v0 + v1) + (v2 + v3);
            float q = v0 * v0 + v1 * v1 + v2 * v2 + v3 * v3;
            #pragma unroll
            for (int m2 = 1; m2 < 16; m2 <<= 1) {
                s += __shfl_xor_sync(0xffffffffu, s, m2);
                q += __shfl_xor_sync(0xffffffffu, q, m2);
            }
            float mean = s * (1.f / 64.f);
            float var = q * (1.f / 64.f) - mean * mean;
            float rstd = rsqrtf(var + 1e-5f);
            int row = ty * 4 + i;
            int grow = base + row;
            if (grow < NN) {
                const float* hr = sH + row * 68 + tx * 4;
                float4 o;
                o.x = silu_f((v0 - mean) * rstd * gv.x + lbv.x + hr[0]);
                o.y = silu_f((v1 - mean) * rstd * gv.y + lbv.y + hr[1]);
                o.z = silu_f((v2 - mean) * rstd * gv.z + lbv.z + hr[2]);
                o.w = silu_f((v3 - mean) * rstd * gv.w + lbv.w + hr[3]);
                *(float4*)(hout + (long)grow * 64 + tx * 4) = o;
            }
        }
    }
}

// ---------------- node MLP: silu(h@W1+b1) -> LN -> @W2+b2, fused ----------------
#define MLP_SMEM ((64 * 256 + 256 * 64 + 32 * 68 + 32 * 260 + 128) * 4)
__global__ __launch_bounds__(256) void mlp_kernel(
    const float* __restrict__ hin, const float* __restrict__ W1, const float* __restrict__ b1,
    const float* __restrict__ gg, const float* __restrict__ bn,
    const float* __restrict__ W2, const float* __restrict__ b2, float* __restrict__ hout) {
    extern __shared__ float smem[];
    float* sW1 = smem;               // 64*256
    float* sW2 = sW1 + 64 * 256;     // 256*64
    float* sA = sW2 + 256 * 64;      // 32 x 68
    float* sT = sA + 32 * 68;        // 32 x 260
    float* sRed = sT + 32 * 260;     // 8 warps * 16
    int tid = threadIdx.x;
    for (int i = tid; i < 64 * 256 / 4; i += 256) ((float4*)sW1)[i] = ((const float4*)W1)[i];
    for (int i = tid; i < 256 * 64 / 4; i += 256) ((float4*)sW2)[i] = ((const float4*)W2)[i];
    int ty = tid >> 6, tx = tid & 63;
    int ry = tid >> 4, cx = tid & 15;
    int warp = tid >> 5;
    float4 b1v = *(const float4*)(b1 + tx * 4);
    float4 gv = *(const float4*)(gg + tx * 4);
    float4 bnv = *(const float4*)(bn + tx * 4);
    float4 b2v = *(const float4*)(b2 + cx * 4);
    const int NT = NN / 32;  // 3125 exact
    for (int t = blockIdx.x; t < NT; t += gridDim.x) {
        __syncthreads();
        int base = t * 32;
        for (int i = tid; i < 32 * 16; i += 256) {
            int r = i >> 4, c = i & 15;
            ((float4*)(sA + r * 68))[c] = ((const float4*)(hin + (long)(base + r) * 64))[c];
        }
        __syncthreads();
        float acc[8][4];
        #pragma unroll
        for (int i = 0; i < 8; i++)
            #pragma unroll
            for (int j = 0; j < 4; j++) acc[i][j] = 0.f;
        #pragma unroll 4
        for (int k = 0; k < 64; k++) {
            float4 wv = *(float4*)(sW1 + k * 256 + tx * 4);
            #pragma unroll
            for (int i = 0; i < 8; i++) {
                float a = sA[(ty * 8 + i) * 68 + k];
                acc[i][0] += a * wv.x; acc[i][1] += a * wv.y;
                acc[i][2] += a * wv.z; acc[i][3] += a * wv.w;
            }
        }
        float ls[8], lq[8];
        #pragma unroll
        for (int i = 0; i < 8; i++) {
            acc[i][0] = silu_f(acc[i][0] + b1v.x);
            acc[i][1] = silu_f(acc[i][1] + b1v.y);
            acc[i][2] = silu_f(acc[i][2] + b1v.z);
            acc[i][3] = silu_f(acc[i][3] + b1v.w);
            ls[i] = (acc[i][0] + acc[i][1]) + (acc[i][2] + acc[i][3]);
            lq[i] = acc[i][0] * acc[i][0] + acc[i][1] * acc[i][1] +
                    acc[i][2] * acc[i][2] + acc[i][3] * acc[i][3];
        }
        #pragma unroll
        for (int i = 0; i < 8; i++) {
            float s = ls[i], q = lq[i];
            #pragma unroll
            for (int m2 = 1; m2 < 32; m2 <<= 1) {
                s += __shfl_xor_sync(0xffffffffu, s, m2);
                q += __shfl_xor_sync(0xffffffffu, q, m2);
            }
            ls[i] = s; lq[i] = q;
        }
        if ((tid & 31) == 0) {
            #pragma unroll
            for (int i = 0; i < 8; i++) {
                sRed[warp * 16 + i * 2] = ls[i];
                sRed[warp * 16 + i * 2 + 1] = lq[i];
            }
        }
        __syncthreads();
        int wb = (ty * 2) * 16;
        #pragma unroll
        for (int i = 0; i < 8; i++) {
            float S = sRed[wb + i * 2] + sRed[wb + 16 + i * 2];
            float Q = sRed[wb + i * 2 + 1] + sRed[wb + 16 + i * 2 + 1];
            float mean = S * (1.f / 256.f);
            float var = Q * (1.f / 256.f) - mean * mean;
            float rstd = rsqrtf(var + 1e-5f);
            float4 n;
            n.x = (acc[i][0] - mean) * rstd * gv.x + bnv.x;
            n.y = (acc[i][1] - mean) * rstd * gv.y + bnv.y;
            n.z = (acc[i][2] - mean) * rstd * gv.z + bnv.z;
            n.w = (acc[i][3] - mean) * rstd * gv.w + bnv.w;
            *(float4*)(sT + (ty * 8 + i) * 260 + tx * 4) = n;
        }
        __syncthreads();
        float a2[2][4];
        #pragma unroll
        for (int i = 0; i < 2; i++)
            #pragma unroll
            for (int j = 0; j < 4; j++) a2[i][j] = 0.f;
        #pragma unroll 8
        for (int k = 0; k < 256; k++) {
            float4 wv = *(float4*)(sW2 + k * 64 + cx * 4);
            float a0 = sT[(ry * 2) * 260 + k];
            float a1 = sT[(ry * 2 + 1) * 260 + k];
            a2[0][0] += a0 * wv.x; a2[0][1] += a0 * wv.y; a2[0][2] += a0 * wv.z; a2[0][3] += a0 * wv.w;
            a2[1][0] += a1 * wv.x; a2[1][1] += a1 * wv.y; a2[1][2] += a1 * wv.z; a2[1][3] += a1 * wv.w;
        }
        int r0 = base + ry * 2;
        float4 o0 = make_float4(a2[0][0] + b2v.x, a2[0][1] + b2v.y, a2[0][2] + b2v.z, a2[0][3] + b2v.w);
        float4 o1 = make_float4(a2[1][0] + b2v.x, a2[1][1] + b2v.y, a2[1][2] + b2v.z, a2[1][3] + b2v.w);
        *(float4*)(hout + (long)r0 * 64 + cx * 4) = o0;
        *(float4*)(hout + (long)(r0 + 1) * 64 + cx * 4) = o1;
    }
}

// ---------------- graph pooling: mean | max | sum | root ----------------
__global__ __launch_bounds__(256) void pool_kernel(const float* __restrict__ h,
                                                   const float* __restrict__ x,
                                                   const int* __restrict__ ptr,
                                                   float* __restrict__ o) {
    int g = blockIdx.x;
    int start = ptr[g], end = ptr[g + 1];
    int tid = threadIdx.x;
    int rl = tid >> 6, d = tid & 63;
    float sm = 0.f, mx = -INFINITY;
    for (int r = start + rl; r < end; r += 4) {
        float v = h[(long)r * 64 + d];
        sm += v;
        mx = fmaxf(mx, v);
    }
    __shared__ float sS[4][64], sM[4][64];
    sS[rl][d] = sm; sM[rl][d] = mx;
    __syncthreads();
    if (tid < 64) {
        float s = sS[0][tid] + sS[1][tid] + sS[2][tid] + sS[3][tid];
        float m = fmaxf(fmaxf(sM[0][tid], sM[1][tid]), fmaxf(sM[2][tid], sM[3][tid]));
        int cnt = end - start;
        float mean = s / (float)(cnt > 0 ? cnt : 1);
        if (m == -INFINITY) m = 0.f;
        o[g * 196 + tid] = mean;
        o[g * 196 + 64 + tid] = m;
        o[g * 196 + 128 + tid] = s;
    }
    if (tid < 4) o[g * 196 + 192 + tid] = x[(long)start * 4 + tid];
}

// ---------------- readout: silu(o@W1+b1) -> LN -> @W2+b2 ----------------
__global__ __launch_bounds__(256) void readout_kernel(
    const float* __restrict__ o, const float* __restrict__ W1, const float* __restrict__ b1,
    const float* __restrict__ gg, const float* __restrict__ bn,
    const float* __restrict__ W2, const float* __restrict__ b2, float* __restrict__ out) {
    int g = blockIdx.x;
    int tid = threadIdx.x;
    __shared__ float so[196];
    __shared__ float red[256];
    __shared__ float ws[8][2];
    __shared__ float stats[2];
    if (tid < 196) so[tid] = o[g * 196 + tid];
    __syncthreads();
    float acc = __ldg(b1 + tid);
    #pragma unroll 4
    for (int k = 0; k < 196; k++) acc += so[k] * __ldg(W1 + k * 256 + tid);
    float s = silu_f(acc);
    float ls = s, lq = s * s;
    #pragma unroll
    for (int m2 = 1; m2 < 32; m2 <<= 1) {
        ls += __shfl_xor_sync(0xffffffffu, ls, m2);
        lq += __shfl_xor_sync(0xffffffffu, lq, m2);
    }
    int w = tid >> 5;
    if ((tid & 31) == 0) { ws[w][0] = ls; ws[w][1] = lq; }
    __syncthreads();
    if (tid == 0) {
        float S = 0.f, Q = 0.f;
        for (int i = 0; i < 8; i++) { S += ws[i][0]; Q += ws[i][1]; }
        stats[0] = S; stats[1] = Q;
    }
    __syncthreads();
    float mean = stats[0] * (1.f / 256.f);
    float var = stats[1] * (1.f / 256.f) - mean * mean;
    float rstd = rsqrtf(var + 1e-5f);
    float n = (s - mean) * rstd * __ldg(gg + tid) + __ldg(bn + tid);
    float4 w2 = *(const float4*)(W2 + tid * 4);
    float p[4] = {n * w2.x, n * w2.y, n * w2.z, n * w2.w};
    for (int j = 0; j < 4; j++) {
        red[tid] = p[j];
        __syncthreads();
        for (int st = 128; st > 0; st >>= 1) {
            if (tid < st) red[tid] += red[tid + st];
            __syncthreads();
        }
        if (tid == 0) out[g * 4 + j] = red[0] + __ldg(b2 + j);
        __syncthreads();
    }
}

// ---------------- launch ----------------
extern "C" void kernel_launch(void* const* d_in, const int* in_sizes, int n_in,
                              void* d_out, int out_size) {
    const float* x      = (const float*)d_in[0];
    const int*   ei     = (const int*)d_in[1];
    const int*   ptr    = (const int*)d_in[3];
    const float* Wl0    = (const float*)d_in[4];
    const float* bl0    = (const float*)d_in[5];
    const float* Wr0    = (const float*)d_in[6];
    const float* Wl     = (const float*)d_in[7];
    const float* bl     = (const float*)d_in[8];
    const float* Wr     = (const float*)d_in[9];
    const float* Wres   = (const float*)d_in[10];
    const float* bres   = (const float*)d_in[11];
    const float* ln_g   = (const float*)d_in[12];
    const float* ln_b   = (const float*)d_in[13];
    const float* mlp_W1 = (const float*)d_in[14];
    const float* mlp_b1 = (const float*)d_in[15];
    const float* mlp_g  = (const float*)d_in[16];
    const float* mlp_bn = (const float*)d_in[17];
    const float* mlp_W2 = (const float*)d_in[18];
    const float* mlp_b2 = (const float*)d_in[19];
    const float* ro_W1  = (const float*)d_in[20];
    const float* ro_b1  = (const float*)d_in[21];
    const float* ro_g   = (const float*)d_in[22];
    const float* ro_bn  = (const float*)d_in[23];
    const float* ro_W2  = (const float*)d_in[24];
    const float* ro_b2  = (const float*)d_in[25];
    float* out = (float*)d_out;

    void* p;
    cudaGetSymbolAddress(&p, g_deg);    int* deg = (int*)p;
    cudaGetSymbolAddress(&p, g_incl);   int* incl = (int*)p;
    cudaGetSymbolAddress(&p, g_rowptr); int* rowptr = (int*)p;
    cudaGetSymbolAddress(&p, g_cur);    int* cur = (int*)p;
    cudaGetSymbolAddress(&p, g_bsums);  int* bsums = (int*)p;
    cudaGetSymbolAddress(&p, g_csr);    int* csr = (int*)p;
    cudaGetSymbolAddress(&p, g_hA);     float* hA = (float*)p;
    cudaGetSymbolAddress(&p, g_hB);     float* hB = (float*)p;
    cudaGetSymbolAddress(&p, g_agg);    float* agg = (float*)p;
    cudaGetSymbolAddress(&p, g_obuf);   float* obuf = (float*)p;

    cudaFuncSetAttribute(sage_gemm_kernel, cudaFuncAttributeMaxDynamicSharedMemorySize, GEMM_SMEM);
    cudaFuncSetAttribute(mlp_kernel, cudaFuncAttributeMaxDynamicSharedMemorySize, MLP_SMEM);

    zero_deg_kernel<<<(NN + 255) / 256, 256>>>(deg);
    hist_kernel<<<(NE + 255) / 256, 256>>>(ei, deg);
    scan1_kernel<<<(NN + 1023) / 1024, 1024>>>(deg, incl, bsums);
    scan2_kernel<<<1, 32>>>(bsums, (NN + 1023) / 1024);
    scan3_kernel<<<(NN + 255) / 256, 256>>>(incl, deg, bsums, rowptr, cur);
    scatter_kernel<<<(NE + 255) / 256, 256>>>(ei, cur, csr);

    layer0_kernel<<<(NN + 3) / 4, 256>>>(x, rowptr, csr, Wl0, bl0, Wr0, Wres, bres,
                                         ln_g, ln_b, hA);

    const float* hin = hA;
    float* hout = hB;
    for (int i = 0; i < 3; i++) {
        agg_kernel<<<(NN + 3) / 4, 256>>>(hin, rowptr, csr, agg);
        sage_gemm_kernel<<<296, 256, GEMM_SMEM>>>(agg, hin, Wl + i * 128 * 64, bl + i * 64,
                                                  Wr + i * 64 * 64, ln_g + (i + 1) * 64,
                                                  ln_b + (i + 1) * 64, hout);
        const float* tmp = hin;
        hin = hout;
        hout = (float*)tmp;
    }
    // hin == hB (final sage output), hout == hA
    mlp_kernel<<<148, 256, MLP_SMEM>>>(hin, mlp_W1, mlp_b1, mlp_g, mlp_bn, mlp_W2, mlp_b2, hout);
    pool_kernel<<<NG, 256>>>(hout, x, ptr, obuf);
    readout_kernel<<<NG, 256>>>(obuf, ro_W1, ro_b1, ro_g, ro_bn, ro_W2, ro_b2, out);
}